// round 1
// baseline (speedup 1.0000x reference)
#include <cuda_runtime.h>
#include <cfloat>

#define R_    512
#define K_    17
#define HIN   56
#define OUT   96
#define NT    192
#define NMAP  (R_ * K_)
#define TMPS  57   // padded row stride for tmp (bank spread)

__device__ __forceinline__ float cubicw(float x) {
    // PyTorch bicubic, A = -0.75
    x = fabsf(x);
    float nearw = (1.25f * x - 2.25f) * x * x + 1.0f;          // (A+2)x^3-(A+3)x^2+1
    float farw  = -0.75f * (((x - 5.0f) * x + 8.0f) * x - 4.0f); // A(x^3-5x^2+8x-4)
    return (x <= 1.0f) ? nearw : farw;   // farw(2)==0, so no explicit x<2 guard needed
}

__global__ __launch_bounds__(NT) void kp_kernel(
    const float* __restrict__ masks,
    const float* __restrict__ boxes,
    float* __restrict__ out)
{
    __shared__ float  s_mask[HIN * HIN];      // 12.5 KB
    __shared__ float  s_tmp[OUT * TMPS];      // 21.9 KB
    __shared__ float4 s_w[OUT];               // 1.5 KB  (4 bicubic weights per out idx)
    __shared__ int    s_base[OUT];            // tap base per out idx
    __shared__ float  s_rv[NT / 32];
    __shared__ int    s_ri[NT / 32];

    const int map = blockIdx.x;
    const int tid = threadIdx.x;

    // ---- tap tables (same for H and W: 56 -> 96) ----
    if (tid < OUT) {
        float s = ((float)tid + 0.5f) * (56.0f / 96.0f) - 0.5f;
        int b = (int)floorf(s);
        s_base[tid] = b;
        float4 w;
        w.x = cubicw(s - (float)(b - 1));
        w.y = cubicw(s - (float)(b    ));
        w.z = cubicw(s - (float)(b + 1));
        w.w = cubicw(s - (float)(b + 2));
        s_w[tid] = w;
    }

    // ---- load 56x56 mask tile (float4, coalesced) ----
    {
        const float4* src4 = (const float4*)(masks + (size_t)map * (HIN * HIN));
        float4* dst4 = (float4*)s_mask;
        #pragma unroll
        for (int i = tid; i < (HIN * HIN) / 4; i += NT) dst4[i] = src4[i];
    }
    __syncthreads();

    // ---- pass 1: vertical resize. thread = (h-group of 32, column j) ----
    {
        int grp = tid >> 6;        // 0..2 -> h in [32*grp, 32*grp+32)
        int j   = tid & 63;
        if (j < HIN) {
            int h0 = grp * 32;
            int b = s_base[h0];
            // init 4-row register window (clamped)
            float m0 = s_mask[max(b - 1, 0) * HIN + j];
            float m1 = s_mask[max(b,     0) * HIN + j];
            float m2 = s_mask[min(max(b + 1, 0), HIN - 1) * HIN + j];
            float m3 = s_mask[min(b + 2, HIN - 1) * HIN + j];
            #pragma unroll
            for (int h = h0; h < h0 + 32; h++) {
                int nb = s_base[h];
                if (nb != b) {                  // base advances by at most 1 (scale < 1)
                    m0 = m1; m1 = m2; m2 = m3;
                    b = nb;
                    m3 = s_mask[min(b + 2, HIN - 1) * HIN + j];
                }
                float4 w = s_w[h];
                float v = m0 * w.x;
                v = fmaf(m1, w.y, v);
                v = fmaf(m2, w.z, v);
                v = fmaf(m3, w.w, v);
                s_tmp[h * TMPS + j] = v;
            }
        }
    }
    __syncthreads();

    // ---- pass 2: horizontal resize fused with argmax. thread = (row h, half) ----
    float best = -FLT_MAX;
    int bestIdx = 0;
    {
        int h    = tid >> 1;       // 0..95
        int half = tid & 1;
        const float* trow = &s_tmp[h * TMPS];
        int w0 = half * 48;
        int b = s_base[w0];
        float t0 = trow[max(b - 1, 0)];
        float t1 = trow[max(b,     0)];
        float t2 = trow[min(max(b + 1, 0), HIN - 1)];
        float t3 = trow[min(b + 2, HIN - 1)];
        #pragma unroll
        for (int w = w0; w < w0 + 48; w++) {
            int nb = s_base[w];
            if (nb != b) {
                t0 = t1; t1 = t2; t2 = t3;
                b = nb;
                t3 = trow[min(b + 2, HIN - 1)];
            }
            float4 ww = s_w[w];
            float v = t0 * ww.x;
            v = fmaf(t1, ww.y, v);
            v = fmaf(t2, ww.z, v);
            v = fmaf(t3, ww.w, v);
            // strict '>' keeps first (lowest-index) max within this thread's
            // monotonically increasing index order
            if (v > best) { best = v; bestIdx = h * OUT + w; }
        }
    }

    // ---- argmax reduction (larger value wins; ties -> smaller linear index) ----
    #pragma unroll
    for (int off = 16; off > 0; off >>= 1) {
        float ov = __shfl_down_sync(0xffffffffu, best, off);
        int   oi = __shfl_down_sync(0xffffffffu, bestIdx, off);
        if (ov > best || (ov == best && oi < bestIdx)) { best = ov; bestIdx = oi; }
    }
    if ((tid & 31) == 0) { s_rv[tid >> 5] = best; s_ri[tid >> 5] = bestIdx; }
    __syncthreads();

    if (tid == 0) {
        #pragma unroll
        for (int i = 1; i < NT / 32; i++) {
            float ov = s_rv[i]; int oi = s_ri[i];
            if (ov > best || (ov == best && oi < bestIdx)) { best = ov; bestIdx = oi; }
        }
        int r = map / K_;
        int k = map - r * K_;
        float b0 = boxes[r * 4 + 0];
        float b1 = boxes[r * 4 + 1];
        float b2 = boxes[r * 4 + 2];
        float b3 = boxes[r * 4 + 3];
        float len0 = fmaxf(b2 - b0, 1.0f);
        float len1 = fmaxf(b3 - b1, 1.0f);
        int y = bestIdx / OUT;
        int x = bestIdx - y * OUT;
        float p0 = ((float)y + 0.5f) * (len0 / (float)OUT) + b0;
        float p1 = ((float)x + 0.5f) * (len1 / (float)OUT) + b1;

        float* pred   = out;                    // [R, 3, K]
        float* scores = out + R_ * 3 * K_;      // [R, K]
        pred[r * 3 * K_ + 0 * K_ + k] = p0;
        pred[r * 3 * K_ + 1 * K_ + k] = p1;
        pred[r * 3 * K_ + 2 * K_ + k] = 1.0f;
        scores[r * K_ + k] = best;
    }
}

extern "C" void kernel_launch(void* const* d_in, const int* in_sizes, int n_in,
                              void* d_out, int out_size) {
    const float* masks = (const float*)d_in[0];   // [512,17,56,56] f32
    const float* boxes = (const float*)d_in[1];   // [512,4] f32
    float* out = (float*)d_out;                   // [512*3*17] preds ++ [512*17] scores
    kp_kernel<<<NMAP, NT>>>(masks, boxes, out);
}

// round 3
// speedup vs baseline: 1.4993x; 1.4993x over previous
#include <cuda_runtime.h>
#include <cfloat>

#define R_    512
#define K_    17
#define HIN   56
#define OUT   96
#define NT    224
#define NMAP  (R_ * K_)
#define MS    57            // padded mask row stride (odd -> bank spread)
#define TS    61            // padded tmp row stride (odd)

// ---- compile-time bicubic helpers (period 12 for 56->96), all host+device ----
__host__ __device__ constexpr float cubicw_c(float x) {
    x = x < 0.f ? -x : x;
    float nearw = (1.25f * x - 2.25f) * x * x + 1.0f;
    float farw  = -0.75f * (((x - 5.0f) * x + 8.0f) * x - 4.0f);
    return x <= 1.0f ? nearw : farw;
}
__host__ __device__ constexpr float srcf(int t) {
    return ((float)t + 0.5f) * (56.0f / 96.0f) - 0.5f;
}
__host__ __device__ constexpr int ifloorf_c(float x) {
    int i = (int)x;
    return ((float)i > x) ? i - 1 : i;
}
__host__ __device__ constexpr int bofs(int t) { return ifloorf_c(srcf(t)); }
// tap base relative to a period-aligned origin: base advances 7 per 12 outputs
__host__ __device__ constexpr int brel(int T) { return 7 * (T / 12) + bofs(T % 12); }

// one unrolled window step: compile-time slide decision + 4-tap dot with
// literal weights; all smem offsets are immediates off pb.
template<int T, int STRIDE>
__device__ __forceinline__ float wstep(float& m0, float& m1, float& m2, float& m3,
                                       const float* __restrict__ pb) {
    if constexpr (T == 0) {
        m0 = pb[(brel(0) - 1) * STRIDE];
        m1 = pb[(brel(0)    ) * STRIDE];
        m2 = pb[(brel(0) + 1) * STRIDE];
        m3 = pb[(brel(0) + 2) * STRIDE];
    } else if constexpr (brel(T) != brel(T - 1)) {   // advances by at most 1
        m0 = m1; m1 = m2; m2 = m3;
        m3 = pb[(brel(T) + 2) * STRIDE];
    }
    constexpr int   t = T % 12;
    constexpr float s = srcf(t);
    constexpr int   b = bofs(t);
    constexpr float W0 = cubicw_c(s - (float)(b - 1));
    constexpr float W1 = cubicw_c(s - (float)(b    ));
    constexpr float W2 = cubicw_c(s - (float)(b + 1));
    constexpr float W3 = cubicw_c(s - (float)(b + 2));
    return fmaf(m3, W3, fmaf(m2, W2, fmaf(m1, W1, m0 * W0)));
}

template<int V> struct IC { static constexpr int v = V; };

template<int T, int N, int STRIDE, typename F>
__device__ __forceinline__ void wloop(float& m0, float& m1, float& m2, float& m3,
                                      const float* __restrict__ pb, F&& f) {
    if constexpr (T < N) {
        float v = wstep<T, STRIDE>(m0, m1, m2, m3, pb);
        f(IC<T>{}, v);
        wloop<T + 1, N, STRIDE>(m0, m1, m2, m3, pb, f);
    }
}

__global__ __launch_bounds__(NT) void kp_kernel(
    const float* __restrict__ masks,
    const float* __restrict__ boxes,
    float* __restrict__ out)
{
    __shared__ float s_mask[60 * MS];      // rows -2..57 (replicated), stride 57
    __shared__ float s_tmp[OUT * TS];      // cols -2..57 stored at c+2, stride 61
    __shared__ float s_rv[NT / 32];
    __shared__ int   s_ri[NT / 32];

    const int map = blockIdx.x;
    const int tid = threadIdx.x;

    // ---- load 56x56 mask with row-replicated padding ----
    {
        const float* g = masks + (size_t)map * (HIN * HIN);
        int r0 = tid / 56;        // 0..3
        int j  = tid - r0 * 56;
        #pragma unroll
        for (int rr = r0; rr < HIN; rr += 4) {
            float v = g[rr * HIN + j];
            s_mask[(rr + 2) * MS + j] = v;
            if (rr == 0)  { s_mask[0 * MS + j] = v; s_mask[1 * MS + j] = v; }
            if (rr == 55) { s_mask[58 * MS + j] = v; s_mask[59 * MS + j] = v; }
        }
    }
    __syncthreads();

    // ---- pass 1: vertical 56->96. thread = (quarter q, col j); 24 rows each ----
    {
        int q = tid / 56;          // 0..3
        int j = tid - q * 56;
        const float* pb = s_mask + (2 + 14 * q) * MS + j;   // 24q rows -> base 14q
        float* dst = s_tmp + (24 * q) * TS + j + 2;
        float m0, m1, m2, m3;
        wloop<0, 24, MS>(m0, m1, m2, m3, pb, [&](auto tc, float v) {
            constexpr int T = decltype(tc)::v;
            dst[T * TS] = v;
            if (j == 0)  { dst[T * TS - 1] = v; dst[T * TS - 2] = v; }
            if (j == 55) { dst[T * TS + 1] = v; dst[T * TS + 2] = v; }
        });
    }
    __syncthreads();

    // ---- pass 2: horizontal 56->96 fused argmax. thread = (row h, half) ----
    float best = -FLT_MAX;
    int bestIdx = 0;
    if (tid < 192) {
        int h    = tid >> 1;
        int half = tid & 1;
        const float* pb = s_tmp + h * TS + 2 + 28 * half;   // 48 cols -> base 28*half
        const int baseIdx = h * OUT + 48 * half;
        float t0, t1, t2, t3;
        wloop<0, 48, 1>(t0, t1, t2, t3, pb, [&](auto tc, float v) {
            constexpr int T = decltype(tc)::v;
            // strict '>' keeps lowest index within this thread's ascending order
            if (v > best) { best = v; bestIdx = baseIdx + T; }
        });
    }

    // ---- argmax reduction (max value; ties -> smaller linear index) ----
    #pragma unroll
    for (int off = 16; off > 0; off >>= 1) {
        float ov = __shfl_down_sync(0xffffffffu, best, off);
        int   oi = __shfl_down_sync(0xffffffffu, bestIdx, off);
        if (ov > best || (ov == best && oi < bestIdx)) { best = ov; bestIdx = oi; }
    }
    if ((tid & 31) == 0) { s_rv[tid >> 5] = best; s_ri[tid >> 5] = bestIdx; }
    __syncthreads();

    if (tid == 0) {
        #pragma unroll
        for (int i = 1; i < NT / 32; i++) {
            float ov = s_rv[i]; int oi = s_ri[i];
            if (ov > best || (ov == best && oi < bestIdx)) { best = ov; bestIdx = oi; }
        }
        int r = map / K_;
        int k = map - r * K_;
        float b0 = boxes[r * 4 + 0];
        float b1 = boxes[r * 4 + 1];
        float b2 = boxes[r * 4 + 2];
        float b3 = boxes[r * 4 + 3];
        float len0 = fmaxf(b2 - b0, 1.0f);
        float len1 = fmaxf(b3 - b1, 1.0f);
        int y = bestIdx / OUT;
        int x = bestIdx - y * OUT;
        float p0 = ((float)y + 0.5f) * (len0 / (float)OUT) + b0;
        float p1 = ((float)x + 0.5f) * (len1 / (float)OUT) + b1;

        float* pred   = out;                    // [R, 3, K]
        float* scores = out + R_ * 3 * K_;      // [R, K]
        pred[r * 3 * K_ + 0 * K_ + k] = p0;
        pred[r * 3 * K_ + 1 * K_ + k] = p1;
        pred[r * 3 * K_ + 2 * K_ + k] = 1.0f;
        scores[r * K_ + k] = best;
    }
}

extern "C" void kernel_launch(void* const* d_in, const int* in_sizes, int n_in,
                              void* d_out, int out_size) {
    const float* masks = (const float*)d_in[0];   // [512,17,56,56] f32
    const float* boxes = (const float*)d_in[1];   // [512,4] f32
    float* out = (float*)d_out;
    kp_kernel<<<NMAP, NT>>>(masks, boxes, out);
}

// round 4
// speedup vs baseline: 1.9227x; 1.2824x over previous
#include <cuda_runtime.h>
#include <cfloat>

#define R_    512
#define K_    17
#define HIN   56
#define OUT   96
#define NT    224
#define NMAP  (R_ * K_)
#define TS    72      // tmp row stride (floats): 16B-aligned, conflict-free vec4

// ---- compile-time bicubic helpers (period 12 for 56->96) ----
__host__ __device__ constexpr float cubicw_c(float x) {
    x = x < 0.f ? -x : x;
    float nearw = (1.25f * x - 2.25f) * x * x + 1.0f;
    float farw  = -0.75f * (((x - 5.0f) * x + 8.0f) * x - 4.0f);
    return x <= 1.0f ? nearw : farw;
}
__host__ __device__ constexpr float srcf(int t) {
    return ((float)t + 0.5f) * (56.0f / 96.0f) - 0.5f;
}
__host__ __device__ constexpr int ifloorf_c(float x) {
    int i = (int)x;
    return ((float)i > x) ? i - 1 : i;
}
__host__ __device__ constexpr int bofs(int t) { return ifloorf_c(srcf(t)); }
__host__ __device__ constexpr int brel(int T) { return 7 * (T / 12) + bofs(T % 12); }
__host__ __device__ constexpr float wgt(int t, int k) {
    return cubicw_c(srcf(t) - (float)(bofs(t) - 1 + k));
}

// clamped (border-replicate) float2 row load straight from gmem
__device__ __forceinline__ float2 ldrow2(const float* __restrict__ g, int row) {
    row = min(max(row, 0), HIN - 1);
    return *(const float2*)(g + row * HIN);
}

// ---------------- pass 1: vertical 56->96, direct from GMEM ----------------
// thread = (g, p): rows 12g..12g+11 (one period block), cols {2p, 2p+1}
template<int T>
__device__ __forceinline__ void pass1_all(
    float2& m0, float2& m1, float2& m2, float2& m3,
    const float* __restrict__ gsrc, int g7, float* __restrict__ dst,
    bool isL, bool isR)
{
    if constexpr (T < 12) {
        if constexpr (T == 0) {
            m0 = ldrow2(gsrc, g7 + bofs(0) - 1);
            m1 = ldrow2(gsrc, g7 + bofs(0)    );
            m2 = ldrow2(gsrc, g7 + bofs(0) + 1);
            m3 = ldrow2(gsrc, g7 + bofs(0) + 2);
        } else if constexpr (bofs(T) != bofs(T - 1)) {   // advances by <=1
            m0 = m1; m1 = m2; m2 = m3;
            m3 = ldrow2(gsrc, g7 + bofs(T) + 2);
        }
        constexpr float W0 = wgt(T, 0), W1 = wgt(T, 1), W2 = wgt(T, 2), W3 = wgt(T, 3);
        float2 v;
        v.x = fmaf(m3.x, W3, fmaf(m2.x, W2, fmaf(m1.x, W1, m0.x * W0)));
        v.y = fmaf(m3.y, W3, fmaf(m2.y, W2, fmaf(m1.y, W1, m0.y * W0)));
        *(float2*)(dst + T * TS) = v;
        if (isL) *(float2*)(dst + T * TS - 2) = make_float2(v.x, v.x);  // cols -2,-1
        if (isR) *(float2*)(dst + T * TS + 2) = make_float2(v.y, v.y);  // cols 56,57
        pass1_all<T + 1>(m0, m1, m2, m3, gsrc, g7, dst, isL, isR);
    }
}

// ---------------- pass 2: horizontal 56->96 + argmax, row in registers -----
// row[i] = tmp col (28*half + i - 2); taps for output T at row[brel(T)+1 .. +4]
template<int T>
__device__ __forceinline__ void pass2_all(
    float* __restrict__ row, const float4* __restrict__ src,
    int baseIdx, float& best, int& bestIdx)
{
    if constexpr (T < 48) {
        constexpr int need = (brel(T) + 4) / 4;                 // highest chunk needed
        if constexpr (T == 0) {
            ((float4*)row)[0] = src[0];
        } else if constexpr (need > (brel(T - 1) + 4) / 4) {    // JIT chunk load
            ((float4*)row)[need] = src[need];
        }
        constexpr int b = brel(T) + 1;
        constexpr int t = T % 12;
        constexpr float W0 = wgt(t, 0), W1 = wgt(t, 1), W2 = wgt(t, 2), W3 = wgt(t, 3);
        float v = fmaf(row[b + 3], W3,
                  fmaf(row[b + 2], W2,
                  fmaf(row[b + 1], W1, row[b] * W0)));
        if (v > best) { best = v; bestIdx = baseIdx + T; }      // strict '>' keeps lowest idx
        pass2_all<T + 1>(row, src, baseIdx, best, bestIdx);
    }
}

__global__ __launch_bounds__(NT) void kp_kernel(
    const float* __restrict__ masks,
    const float* __restrict__ boxes,
    float* __restrict__ out)
{
    __shared__ float s_tmp[OUT * TS];     // 27.6 KB; col c stored at c+2, stride 72
    __shared__ float s_rv[NT / 32];
    __shared__ int   s_ri[NT / 32];

    const int map = blockIdx.x;
    const int tid = threadIdx.x;

    // ---- pass 1 (no smem staging of the mask) ----
    {
        int g = tid / 28;          // 0..7 : row block (12 output rows)
        int p = tid - g * 28;      // 0..27: column pair {2p, 2p+1}
        const float* gsrc = masks + (size_t)map * (HIN * HIN) + 2 * p;
        float* dst = s_tmp + (12 * g) * TS + 2 + 2 * p;
        float2 m0, m1, m2, m3;
        pass1_all<0>(m0, m1, m2, m3, gsrc, 7 * g, dst, p == 0, p == 27);
    }
    __syncthreads();

    // ---- pass 2 fused with per-thread argmax ----
    float best = -FLT_MAX;
    int bestIdx = 0;
    if (tid < 192) {
        int h    = tid >> 1;
        int half = tid & 1;
        const float4* src = (const float4*)(s_tmp + h * TS + 28 * half);
        float row[32];
        pass2_all<0>(row, src, h * OUT + 48 * half, best, bestIdx);
    }

    // ---- argmax reduction (max value; ties -> smaller linear index) ----
    #pragma unroll
    for (int off = 16; off > 0; off >>= 1) {
        float ov = __shfl_down_sync(0xffffffffu, best, off);
        int   oi = __shfl_down_sync(0xffffffffu, bestIdx, off);
        if (ov > best || (ov == best && oi < bestIdx)) { best = ov; bestIdx = oi; }
    }
    if ((tid & 31) == 0) { s_rv[tid >> 5] = best; s_ri[tid >> 5] = bestIdx; }
    __syncthreads();

    if (tid == 0) {
        #pragma unroll
        for (int i = 1; i < NT / 32; i++) {
            float ov = s_rv[i]; int oi = s_ri[i];
            if (ov > best || (ov == best && oi < bestIdx)) { best = ov; bestIdx = oi; }
        }
        int r = map / K_;
        int k = map - r * K_;
        float b0 = boxes[r * 4 + 0];
        float b1 = boxes[r * 4 + 1];
        float b2 = boxes[r * 4 + 2];
        float b3 = boxes[r * 4 + 3];
        float len0 = fmaxf(b2 - b0, 1.0f);
        float len1 = fmaxf(b3 - b1, 1.0f);
        int y = bestIdx / OUT;
        int x = bestIdx - y * OUT;
        float p0 = ((float)y + 0.5f) * (len0 / (float)OUT) + b0;
        float p1 = ((float)x + 0.5f) * (len1 / (float)OUT) + b1;

        float* pred   = out;                    // [R, 3, K]
        float* scores = out + R_ * 3 * K_;      // [R, K]
        pred[r * 3 * K_ + 0 * K_ + k] = p0;
        pred[r * 3 * K_ + 1 * K_ + k] = p1;
        pred[r * 3 * K_ + 2 * K_ + k] = 1.0f;
        scores[r * K_ + k] = best;
    }
}

extern "C" void kernel_launch(void* const* d_in, const int* in_sizes, int n_in,
                              void* d_out, int out_size) {
    const float* masks = (const float*)d_in[0];   // [512,17,56,56] f32
    const float* boxes = (const float*)d_in[1];   // [512,4] f32
    float* out = (float*)d_out;
    kp_kernel<<<NMAP, NT>>>(masks, boxes, out);
}

// round 5
// speedup vs baseline: 1.9313x; 1.0045x over previous
#include <cuda_runtime.h>
#include <cfloat>

#define R_    512
#define K_    17
#define HIN   56
#define OUT   96
#define NT    192
#define NMAP  (R_ * K_)
#define TS    72      // tmp row stride in words
#define PAD   4       // col c stored at word c+4 (keeps STS.128 & LDS.128 aligned)

// ---- compile-time bicubic helpers (period 12 for 56->96) ----
__host__ __device__ constexpr float cubicw_c(float x) {
    x = x < 0.f ? -x : x;
    float nearw = (1.25f * x - 2.25f) * x * x + 1.0f;
    float farw  = -0.75f * (((x - 5.0f) * x + 8.0f) * x - 4.0f);
    return x <= 1.0f ? nearw : farw;
}
__host__ __device__ constexpr float srcf(int t) {
    return ((float)t + 0.5f) * (56.0f / 96.0f) - 0.5f;
}
__host__ __device__ constexpr int ifloorf_c(float x) {
    int i = (int)x;
    return ((float)i > x) ? i - 1 : i;
}
__host__ __device__ constexpr int bofs(int t) { return ifloorf_c(srcf(t)); }
__host__ __device__ constexpr int brel(int T) { return 7 * (T / 12) + bofs(T % 12); }
__host__ __device__ constexpr float wgt(int t, int k) {
    return cubicw_c(srcf(t) - (float)(bofs(t) - 1 + k));
}

// runtime-indexable copy of the SAME constexpr tables (bit-identical weights)
struct WTab { float w[12][4]; int b[12]; };
__host__ __device__ constexpr WTab make_wtab() {
    WTab r{};
    for (int t = 0; t < 12; ++t) {
        r.b[t] = bofs(t);
        for (int k = 0; k < 4; ++k) r.w[t][k] = wgt(t, k);
    }
    return r;
}
__constant__ WTab cWT = make_wtab();

// clamped (border-replicate) float4 row load straight from gmem
__device__ __forceinline__ float4 ldrow4(const float* __restrict__ g, int row) {
    row = min(max(row, 0), HIN - 1);
    return *(const float4*)(g + row * HIN);
}

// ---------------- pass 1: vertical 56->96, direct from GMEM, float4 lanes ----
template<int T>
__device__ __forceinline__ void p1_all(
    float4& m0, float4& m1, float4& m2, float4& m3,
    const float* __restrict__ gsrc, int g7, float* __restrict__ dst)
{
    if constexpr (T < 12) {
        if constexpr (T == 0) {
            m0 = ldrow4(gsrc, g7 + bofs(0) - 1);
            m1 = ldrow4(gsrc, g7 + bofs(0)    );
            m2 = ldrow4(gsrc, g7 + bofs(0) + 1);
            m3 = ldrow4(gsrc, g7 + bofs(0) + 2);
        } else if constexpr (bofs(T) != bofs(T - 1)) {   // advances by <=1
            m0 = m1; m1 = m2; m2 = m3;
            m3 = ldrow4(gsrc, g7 + bofs(T) + 2);
        }
        constexpr float W0 = wgt(T, 0), W1 = wgt(T, 1), W2 = wgt(T, 2), W3 = wgt(T, 3);
        float4 v;
        v.x = fmaf(m3.x, W3, fmaf(m2.x, W2, fmaf(m1.x, W1, m0.x * W0)));
        v.y = fmaf(m3.y, W3, fmaf(m2.y, W2, fmaf(m1.y, W1, m0.y * W0)));
        v.z = fmaf(m3.z, W3, fmaf(m2.z, W2, fmaf(m1.z, W1, m0.z * W0)));
        v.w = fmaf(m3.w, W3, fmaf(m2.w, W2, fmaf(m1.w, W1, m0.w * W0)));
        *(float4*)(dst + T * TS) = v;
        p1_all<T + 1>(m0, m1, m2, m3, gsrc, g7, dst);
    }
}

// ---------------- pass 2 helpers: row[j] = word 28*half + j of the tmp row ----
// tap index j for output T (thread-local 0..47), tap k: j = brel(T)+3+k
template<int C, int HI>
__device__ __forceinline__ void p2chunks(float* __restrict__ row, const float4* __restrict__ src) {
    if constexpr (C <= HI) {
        float4 q = src[C];
        row[4 * C + 0] = q.x; row[4 * C + 1] = q.y;
        row[4 * C + 2] = q.z; row[4 * C + 3] = q.w;
        p2chunks<C + 1, HI>(row, src);
    }
}
template<int T>
__device__ __forceinline__ void p2load(float* __restrict__ row, const float4* __restrict__ src) {
    constexpr int hi = (brel(T) + 6) / 4;
    constexpr int lo = (T == 0) ? 0 : (brel(T - 1) + 6) / 4 + 1;
    p2chunks<lo, hi>(row, src);
}
template<int T>
__device__ __forceinline__ float p2v(const float* __restrict__ row) {
    constexpr int   t = T % 12;
    constexpr int   b = brel(T) + 3;
    constexpr float W0 = wgt(t, 0), W1 = wgt(t, 1), W2 = wgt(t, 2), W3 = wgt(t, 3);
    return fmaf(row[b + 3], W3, fmaf(row[b + 2], W2, fmaf(row[b + 1], W1, row[b] * W0)));
}
template<int G>
__device__ __forceinline__ void p2group(
    float* __restrict__ row, const float4* __restrict__ src,
    float& best, int& bestGS, int baseIdx)
{
    if constexpr (G < 12) {
        p2load<4 * G + 0>(row, src); float v0 = p2v<4 * G + 0>(row);
        p2load<4 * G + 1>(row, src); float v1 = p2v<4 * G + 1>(row);
        p2load<4 * G + 2>(row, src); float v2 = p2v<4 * G + 2>(row);
        p2load<4 * G + 3>(row, src); float v3 = p2v<4 * G + 3>(row);
        float gm = fmaxf(fmaxf(v0, v1), fmaxf(v2, v3));
        // strict '>' keeps earliest group on value ties (first-index semantics)
        if (gm > best) { best = gm; bestGS = baseIdx + 4 * G; }
        p2group<G + 1>(row, src, best, bestGS, baseIdx);
    }
}

__global__ __launch_bounds__(NT) void kp_kernel(
    const float* __restrict__ masks,
    const float* __restrict__ boxes,
    float* __restrict__ out)
{
    __shared__ float s_tmp[OUT * TS];     // 27.6 KB; col c at word c+PAD
    __shared__ float s_rv[NT / 32];
    __shared__ int   s_ri[NT / 32];

    const int map = blockIdx.x;
    const int tid = threadIdx.x;

    // ---- pass 1: 112 threads, each (row-block g, column quad q) ----
    if (tid < 112) {
        int g = tid / 14;          // 0..7 : 12 output rows each
        int q = tid - g * 14;      // 0..13: cols 4q..4q+3
        const float* gsrc = masks + (size_t)map * (HIN * HIN) + 4 * q;
        float* dst = s_tmp + (12 * g) * TS + PAD + 4 * q;
        float4 m0, m1, m2, m3;
        p1_all<0>(m0, m1, m2, m3, gsrc, 7 * g, dst);
    }
    __syncthreads();

    // ---- border fill: replicate col0 -> words 2,3 ; col55 -> words 60,61 ----
    {
        int h = (tid < 96) ? tid : tid - 96;
        float* rowp = s_tmp + h * TS;
        if (tid < 96) {
            float v = rowp[PAD + 0];
            *(float2*)(rowp + 2) = make_float2(v, v);
        } else {
            float v = rowp[PAD + 55];
            *(float2*)(rowp + PAD + 56) = make_float2(v, v);
        }
    }
    __syncthreads();

    // ---- pass 2: horizontal 56->96 with grouped argmax ----
    float best = -FLT_MAX;
    int bestGS = 0x7fffffff;
    {
        int h    = tid >> 1;
        int half = tid & 1;
        const float4* src = (const float4*)(s_tmp + h * TS + 28 * half);
        float row[36];
        p2group<0>(row, src, best, bestGS, h * OUT + 48 * half);
    }

    // ---- reduction on (value, groupStart): max value, ties -> smaller gs ----
    #pragma unroll
    for (int off = 16; off > 0; off >>= 1) {
        float ov = __shfl_down_sync(0xffffffffu, best, off);
        int   og = __shfl_down_sync(0xffffffffu, bestGS, off);
        if (ov > best || (ov == best && og < bestGS)) { best = ov; bestGS = og; }
    }
    if ((tid & 31) == 0) { s_rv[tid >> 5] = best; s_ri[tid >> 5] = bestGS; }
    __syncthreads();

    if (tid == 0) {
        #pragma unroll
        for (int i = 1; i < NT / 32; i++) {
            float ov = s_rv[i]; int og = s_ri[i];
            if (ov > best || (ov == best && og < bestGS)) { best = ov; bestGS = og; }
        }
        // ---- exact within-group index recovery (bit-identical recompute) ----
        int gs = bestGS;
        int hh = gs / OUT;
        int w0 = gs - hh * OUT;
        int found = 0;
        bool got = false;
        #pragma unroll
        for (int i = 3; i >= 0; i--) {       // descending: final 'found' = first match
            int T = w0 + i;
            int d = T / 12;
            int t = T - 12 * d;
            const float* p = s_tmp + hh * TS + 7 * d + cWT.b[t] + 3;
            float v = fmaf(p[3], cWT.w[t][3],
                      fmaf(p[2], cWT.w[t][2],
                      fmaf(p[1], cWT.w[t][1], p[0] * cWT.w[t][0])));
            if (v == best) { found = i; got = true; }
        }
        (void)got;
        int bestIdx = gs + found;

        int r = map / K_;
        int k = map - r * K_;
        float b0 = boxes[r * 4 + 0];
        float b1 = boxes[r * 4 + 1];
        float b2 = boxes[r * 4 + 2];
        float b3 = boxes[r * 4 + 3];
        float len0 = fmaxf(b2 - b0, 1.0f);
        float len1 = fmaxf(b3 - b1, 1.0f);
        int y = bestIdx / OUT;
        int x = bestIdx - y * OUT;
        float p0 = ((float)y + 0.5f) * (len0 / (float)OUT) + b0;
        float p1 = ((float)x + 0.5f) * (len1 / (float)OUT) + b1;

        float* pred   = out;                    // [R, 3, K]
        float* scores = out + R_ * 3 * K_;      // [R, K]
        pred[r * 3 * K_ + 0 * K_ + k] = p0;
        pred[r * 3 * K_ + 1 * K_ + k] = p1;
        pred[r * 3 * K_ + 2 * K_ + k] = 1.0f;
        scores[r * K_ + k] = best;
    }
}

extern "C" void kernel_launch(void* const* d_in, const int* in_sizes, int n_in,
                              void* d_out, int out_size) {
    const float* masks = (const float*)d_in[0];   // [512,17,56,56] f32
    const float* boxes = (const float*)d_in[1];   // [512,4] f32
    float* out = (float*)d_out;
    kp_kernel<<<NMAP, NT>>>(masks, boxes, out);
}

// round 7
// speedup vs baseline: 2.0222x; 1.0470x over previous
#include <cuda_runtime.h>
#include <cfloat>
#include <cstdint>

#define R_    512
#define K_    17
#define HIN   56
#define OUT   96
#define NT    192
#define MPC   4                    // maps per CTA
#define NMAP  (R_ * K_)
#define TS    72                   // tmp row stride in words
#define PAD   4                    // col c stored at word c+4

// ---- compile-time bicubic helpers (period 12 for 56->96) ----
__host__ __device__ constexpr float cubicw_c(float x) {
    x = x < 0.f ? -x : x;
    float nearw = (1.25f * x - 2.25f) * x * x + 1.0f;
    float farw  = -0.75f * (((x - 5.0f) * x + 8.0f) * x - 4.0f);
    return x <= 1.0f ? nearw : farw;
}
__host__ __device__ constexpr float srcf(int t) {
    return ((float)t + 0.5f) * (56.0f / 96.0f) - 0.5f;
}
__host__ __device__ constexpr int ifloorf_c(float x) {
    int i = (int)x;
    return ((float)i > x) ? i - 1 : i;
}
__host__ __device__ constexpr int bofs(int t) { return ifloorf_c(srcf(t)); }
__host__ __device__ constexpr int brel(int T) { return 7 * (T / 12) + bofs(T % 12); }
__host__ __device__ constexpr float wgt(int t, int k) {
    return cubicw_c(srcf(t) - (float)(bofs(t) - 1 + k));
}

struct WTab { float w[12][4]; int b[12]; };
__host__ __device__ constexpr WTab make_wtab() {
    WTab r{};
    for (int t = 0; t < 12; ++t) {
        r.b[t] = bofs(t);
        for (int k = 0; k < 4; ++k) r.w[t][k] = wgt(t, k);
    }
    return r;
}
__constant__ WTab cWT = make_wtab();

// ---- cp.async 16B helper ----
__device__ __forceinline__ void cp16(unsigned int sdst, const void* gsrc) {
    asm volatile("cp.async.cg.shared.global [%0], [%1], 16;" :: "r"(sdst), "l"(gsrc));
}
__device__ __forceinline__ void cp_commit() {
    asm volatile("cp.async.commit_group;");
}
__device__ __forceinline__ void cp_wait0() {
    asm volatile("cp.async.wait_group 0;");
}

// clamped row load from the smem-staged mask
__device__ __forceinline__ float4 ldrow4s(const float* __restrict__ sm, int row) {
    row = min(max(row, 0), HIN - 1);
    return *(const float4*)(sm + row * HIN);
}

// ---------------- pass 1: vertical 56->96 from smem mask, float4 lanes ----
template<int T>
__device__ __forceinline__ void p1_all(
    float4& m0, float4& m1, float4& m2, float4& m3,
    const float* __restrict__ sm, int g7, float* __restrict__ dst,
    bool isL, bool isR)
{
    if constexpr (T < 12) {
        if constexpr (T == 0) {
            m0 = ldrow4s(sm, g7 + bofs(0) - 1);
            m1 = ldrow4s(sm, g7 + bofs(0)    );
            m2 = ldrow4s(sm, g7 + bofs(0) + 1);
            m3 = ldrow4s(sm, g7 + bofs(0) + 2);
        } else if constexpr (bofs(T) != bofs(T - 1)) {   // advances by <=1
            m0 = m1; m1 = m2; m2 = m3;
            m3 = ldrow4s(sm, g7 + bofs(T) + 2);
        }
        constexpr float W0 = wgt(T, 0), W1 = wgt(T, 1), W2 = wgt(T, 2), W3 = wgt(T, 3);
        float4 v;
        v.x = fmaf(m3.x, W3, fmaf(m2.x, W2, fmaf(m1.x, W1, m0.x * W0)));
        v.y = fmaf(m3.y, W3, fmaf(m2.y, W2, fmaf(m1.y, W1, m0.y * W0)));
        v.z = fmaf(m3.z, W3, fmaf(m2.z, W2, fmaf(m1.z, W1, m0.z * W0)));
        v.w = fmaf(m3.w, W3, fmaf(m2.w, W2, fmaf(m1.w, W1, m0.w * W0)));
        *(float4*)(dst + T * TS) = v;
        if (isL) *(float2*)(dst + T * TS - 2) = make_float2(v.x, v.x); // cols -2,-1
        if (isR) *(float2*)(dst + T * TS + 4) = make_float2(v.w, v.w); // cols 56,57
        p1_all<T + 1>(m0, m1, m2, m3, sm, g7, dst, isL, isR);
    }
}

// ---------------- pass 2 helpers ----------------
template<int C, int HI>
__device__ __forceinline__ void p2chunks(float* __restrict__ row, const float4* __restrict__ src) {
    if constexpr (C <= HI) {
        float4 q = src[C];
        row[4 * C + 0] = q.x; row[4 * C + 1] = q.y;
        row[4 * C + 2] = q.z; row[4 * C + 3] = q.w;
        p2chunks<C + 1, HI>(row, src);
    }
}
template<int T>
__device__ __forceinline__ void p2load(float* __restrict__ row, const float4* __restrict__ src) {
    constexpr int hi = (brel(T) + 6) / 4;
    constexpr int lo = (T == 0) ? 0 : (brel(T - 1) + 6) / 4 + 1;
    p2chunks<lo, hi>(row, src);
}
template<int T>
__device__ __forceinline__ float p2v(const float* __restrict__ row) {
    constexpr int   t = T % 12;
    constexpr int   b = brel(T) + 3;
    constexpr float W0 = wgt(t, 0), W1 = wgt(t, 1), W2 = wgt(t, 2), W3 = wgt(t, 3);
    return fmaf(row[b + 3], W3, fmaf(row[b + 2], W2, fmaf(row[b + 1], W1, row[b] * W0)));
}
template<int G>
__device__ __forceinline__ void p2group(
    float* __restrict__ row, const float4* __restrict__ src,
    float& best, int& bestGS, int baseIdx)
{
    if constexpr (G < 12) {
        p2load<4 * G + 0>(row, src); float v0 = p2v<4 * G + 0>(row);
        p2load<4 * G + 1>(row, src); float v1 = p2v<4 * G + 1>(row);
        p2load<4 * G + 2>(row, src); float v2 = p2v<4 * G + 2>(row);
        p2load<4 * G + 3>(row, src); float v3 = p2v<4 * G + 3>(row);
        float gm = fmaxf(fmaxf(v0, v1), fmaxf(v2, v3));
        if (gm > best) { best = gm; bestGS = baseIdx + 4 * G; } // strict '>': earliest group
        p2group<G + 1>(row, src, best, bestGS, baseIdx);
    }
}

__global__ __launch_bounds__(NT) void kp_kernel(
    const float* __restrict__ masks,
    const float* __restrict__ boxes,
    float* __restrict__ out)
{
    __shared__ float s_mask[HIN * HIN];    // 12.25 KB (cp.async staged)
    __shared__ float s_tmp[OUT * TS];      // 27.6 KB
    __shared__ float s_rv[NT / 32];
    __shared__ int   s_ri[NT / 32];

    const int tid  = threadIdx.x;
    const int map0 = blockIdx.x * MPC;

    unsigned int smask_u = (unsigned int)__cvta_generic_to_shared(s_mask);

    // prologue: prefetch map0's mask (784 float4 = 12.25 KB)
    {
        const float4* g = (const float4*)(masks + (size_t)map0 * (HIN * HIN));
        #pragma unroll
        for (int i = 0; i < 4; i++)
            cp16(smask_u + (tid + i * NT) * 16, g + tid + i * NT);
        if (tid < 16)
            cp16(smask_u + (768 + tid) * 16, g + 768 + tid);
        cp_commit();
    }

    for (int m = 0; m < MPC; m++) {
        const int map = map0 + m;

        cp_wait0();
        __syncthreads();    // mask visible to all; protects s_tmp/s_rv reuse

        // ---- pass 1: 112 threads, (row-block g, column quad q), smem->smem ----
        if (tid < 112) {
            int g = tid / 14;          // 0..7 : 12 output rows each
            int q = tid - g * 14;      // 0..13: cols 4q..4q+3
            const float* sm = s_mask + 4 * q;
            float* dst = s_tmp + (12 * g) * TS + PAD + 4 * q;
            float4 m0, m1, m2, m3;
            p1_all<0>(m0, m1, m2, m3, sm, 7 * g, dst, q == 0, q == 13);
        }
        __syncthreads();

        // ---- prefetch next map's mask (overlaps pass 2) ----
        if (m + 1 < MPC) {
            const float4* g = (const float4*)(masks + (size_t)(map + 1) * (HIN * HIN));
            #pragma unroll
            for (int i = 0; i < 4; i++)
                cp16(smask_u + (tid + i * NT) * 16, g + tid + i * NT);
            if (tid < 16)
                cp16(smask_u + (768 + tid) * 16, g + 768 + tid);
        }
        cp_commit();

        // ---- pass 2: horizontal 56->96 with grouped argmax ----
        float best = -FLT_MAX;
        int bestGS = 0x7fffffff;
        {
            int h    = tid >> 1;
            int half = tid & 1;
            const float4* src = (const float4*)(s_tmp + h * TS + 28 * half);
            float row[36];
            p2group<0>(row, src, best, bestGS, h * OUT + 48 * half);
        }

        #pragma unroll
        for (int off = 16; off > 0; off >>= 1) {
            float ov = __shfl_down_sync(0xffffffffu, best, off);
            int   og = __shfl_down_sync(0xffffffffu, bestGS, off);
            if (ov > best || (ov == best && og < bestGS)) { best = ov; bestGS = og; }
        }
        if ((tid & 31) == 0) { s_rv[tid >> 5] = best; s_ri[tid >> 5] = bestGS; }
        __syncthreads();

        if (tid == 0) {
            #pragma unroll
            for (int i = 1; i < NT / 32; i++) {
                float ov = s_rv[i]; int og = s_ri[i];
                if (ov > best || (ov == best && og < bestGS)) { best = ov; bestGS = og; }
            }
            // exact within-group index recovery (bit-identical recompute)
            int gs = bestGS;
            int hh = gs / OUT;
            int w0 = gs - hh * OUT;
            int found = 0;
            #pragma unroll
            for (int i = 3; i >= 0; i--) {    // descending: final 'found' = first match
                int T = w0 + i;
                int d = T / 12;
                int t = T - 12 * d;
                const float* p = s_tmp + hh * TS + 7 * d + cWT.b[t] + 3;
                float v = fmaf(p[3], cWT.w[t][3],
                          fmaf(p[2], cWT.w[t][2],
                          fmaf(p[1], cWT.w[t][1], p[0] * cWT.w[t][0])));
                if (v == best) { found = i; }
            }
            int bestIdx = gs + found;

            int r = map / K_;
            int k = map - r * K_;
            float b0 = boxes[r * 4 + 0];
            float b1 = boxes[r * 4 + 1];
            float b2 = boxes[r * 4 + 2];
            float b3 = boxes[r * 4 + 3];
            float len0 = fmaxf(b2 - b0, 1.0f);
            float len1 = fmaxf(b3 - b1, 1.0f);
            int y = bestIdx / OUT;
            int x = bestIdx - y * OUT;
            float p0 = ((float)y + 0.5f) * (len0 / (float)OUT) + b0;
            float p1 = ((float)x + 0.5f) * (len1 / (float)OUT) + b1;

            float* pred   = out;                    // [R, 3, K]
            float* scores = out + R_ * 3 * K_;      // [R, K]
            pred[r * 3 * K_ + 0 * K_ + k] = p0;
            pred[r * 3 * K_ + 1 * K_ + k] = p1;
            pred[r * 3 * K_ + 2 * K_ + k] = 1.0f;
            scores[r * K_ + k] = best;
        }
    }
}

extern "C" void kernel_launch(void* const* d_in, const int* in_sizes, int n_in,
                              void* d_out, int out_size) {
    const float* masks = (const float*)d_in[0];   // [512,17,56,56] f32
    const float* boxes = (const float*)d_in[1];   // [512,4] f32
    float* out = (float*)d_out;
    kp_kernel<<<NMAP / MPC, NT>>>(masks, boxes, out);
}